// round 1
// baseline (speedup 1.0000x reference)
#include <cuda_runtime.h>
#include <math.h>

#define CC   256
#define NSP  16384
#define BB   8
#define EPS  1e-5f
#define KSPLIT 32

// ---------------- scratch (device globals; no allocs allowed) ----------------
__device__ float g_E[(size_t)BB * CC * NSP];   // exp(Wk @ x)  [b, c, n]   128 MB
__device__ float g_rowsum[BB * CC];            // sum_n exp(k) (then reciprocal)
__device__ float g_St[BB * CC * CC];           // St[b][e][c] = sum_n x[e,n] E[c,n]
__device__ float g_R[BB * CC * CC];            // R = P^T @ Wq
__device__ float g_M[BB * CC * CC];            // M = inv * (W2 @ R)
__device__ float g_W2[CC * CC];                // W2 = w_proj @ Wv

// row/col index within 128-tile for the 8x8 micro-tile (i<4: near block, i>=4: +64)
__device__ __forceinline__ int rc_map(int tcoord, int i) {
    return (i < 4) ? (tcoord * 4 + i) : (64 + tcoord * 4 + (i - 4));
}

// ---------------- 128x128 CTA-tile GEMM core, 256 threads, 8x8 per thread ----
// NT=false: C = A[128 x K] * B[K x 128]        (A row-major lda, B row-major ldb)
// NT=true : C = A[128 x K] * B[128 x K]^T      (both k-contiguous)
// BSCALE (only !NT): B row k scaled by bscale[k].
template<bool NT, bool BSCALE>
__device__ __forceinline__ void core128(
    const float* __restrict__ A, int lda,
    const float* __restrict__ B, int ldb,
    const float* __restrict__ bscale,
    int kbeg, int kend, float acc[8][8])
{
    __shared__ __align__(16) float As[8][132];
    __shared__ __align__(16) float Bs[8][132];

    const int t    = threadIdx.x;
    const int tx   = t & 15;
    const int ty   = t >> 4;
    const int arow = t >> 1;          // 0..127
    const int ak   = (t & 1) << 2;    // 0 or 4
    const int brow = t >> 5;          // 0..7   (NN B load)
    const int bcol = (t & 31) << 2;   // 0..124 (NN B load)

    for (int k0 = kbeg; k0 < kend; k0 += 8) {
        float4 a4 = *(const float4*)(A + (size_t)arow * lda + k0 + ak);
        float4 b4;
        if (NT) {
            b4 = *(const float4*)(B + (size_t)arow * ldb + k0 + ak);
        } else {
            b4 = *(const float4*)(B + (size_t)(k0 + brow) * ldb + bcol);
            if (BSCALE) {
                float s = bscale[k0 + brow];
                b4.x *= s; b4.y *= s; b4.z *= s; b4.w *= s;
            }
        }
        __syncthreads();
        As[ak + 0][arow] = a4.x; As[ak + 1][arow] = a4.y;
        As[ak + 2][arow] = a4.z; As[ak + 3][arow] = a4.w;
        if (NT) {
            Bs[ak + 0][arow] = b4.x; Bs[ak + 1][arow] = b4.y;
            Bs[ak + 2][arow] = b4.z; Bs[ak + 3][arow] = b4.w;
        } else {
            *(float4*)&Bs[brow][bcol] = b4;
        }
        __syncthreads();

        #pragma unroll
        for (int kk = 0; kk < 8; kk++) {
            float4 a0 = *(const float4*)&As[kk][ty << 2];
            float4 a1 = *(const float4*)&As[kk][(ty << 2) + 64];
            float4 b0 = *(const float4*)&Bs[kk][tx << 2];
            float4 b1 = *(const float4*)&Bs[kk][(tx << 2) + 64];
            float av[8] = {a0.x, a0.y, a0.z, a0.w, a1.x, a1.y, a1.z, a1.w};
            float bv[8] = {b0.x, b0.y, b0.z, b0.w, b1.x, b1.y, b1.z, b1.w};
            #pragma unroll
            for (int i = 0; i < 8; i++)
                #pragma unroll
                for (int j = 0; j < 8; j++)
                    acc[i][j] += av[i] * bv[j];
        }
    }
}

// ---------------- K1: E = exp(Wk @ x), row sums via atomics ----------------
__global__ void __launch_bounds__(256)
k_exp(const float* __restrict__ x, const float* __restrict__ w_qkv)
{
    const int b  = blockIdx.z;
    const int m0 = blockIdx.y * 128;
    const int n0 = blockIdx.x * 128;
    const float* A  = w_qkv + (size_t)(CC + m0) * CC;          // Wk rows
    const float* Bm = x + (size_t)b * CC * NSP + n0;

    float acc[8][8] = {};
    core128<false, false>(A, CC, Bm, NSP, nullptr, 0, CC, acc);

    const int tx = threadIdx.x & 15, ty = threadIdx.x >> 4;
    float* Eb = g_E + (size_t)b * CC * NSP;

    #pragma unroll
    for (int i = 0; i < 8; i++) {
        const int r = m0 + rc_map(ty, i);
        float4 v0, v1;
        v0.x = __expf(acc[i][0]); v0.y = __expf(acc[i][1]);
        v0.z = __expf(acc[i][2]); v0.w = __expf(acc[i][3]);
        v1.x = __expf(acc[i][4]); v1.y = __expf(acc[i][5]);
        v1.z = __expf(acc[i][6]); v1.w = __expf(acc[i][7]);
        *(float4*)(Eb + (size_t)r * NSP + n0 + (tx << 2))      = v0;
        *(float4*)(Eb + (size_t)r * NSP + n0 + 64 + (tx << 2)) = v1;
        float s = v0.x + v0.y + v0.z + v0.w + v1.x + v1.y + v1.z + v1.w;
        #pragma unroll
        for (int off = 8; off > 0; off >>= 1)
            s += __shfl_down_sync(0xffffffffu, s, off);
        if (tx == 0) atomicAdd(&g_rowsum[b * CC + r], s);
    }
}

// ---------------- invert rowsums ----------------
__global__ void k_inv()
{
    int i = blockIdx.x * 256 + threadIdx.x;
    if (i < BB * CC) g_rowsum[i] = 1.0f / g_rowsum[i];
}

// ---------------- K2: St[b][e][c] += sum_n x[e,n] * E[c,n]  (split-K) -------
__global__ void __launch_bounds__(256)
k_st(const float* __restrict__ x)
{
    const int c0 = blockIdx.x * 128;
    const int e0 = blockIdx.y * 128;
    const int zz = blockIdx.z;
    const int b  = zz / KSPLIT;
    const int ks = zz % KSPLIT;
    const int kbeg = ks * (NSP / KSPLIT);
    const int kend = kbeg + (NSP / KSPLIT);

    const float* A  = x   + (size_t)b * CC * NSP + (size_t)e0 * NSP;
    const float* Bm = g_E + (size_t)b * CC * NSP + (size_t)c0 * NSP;

    float acc[8][8] = {};
    core128<true, false>(A, NSP, Bm, NSP, nullptr, kbeg, kend, acc);

    const int tx = threadIdx.x & 15, ty = threadIdx.x >> 4;
    float* Sb = g_St + (size_t)b * CC * CC;
    #pragma unroll
    for (int i = 0; i < 8; i++) {
        const int r = e0 + rc_map(ty, i);
        #pragma unroll
        for (int j = 0; j < 8; j++) {
            const int c = c0 + rc_map(tx, j);
            atomicAdd(&Sb[r * CC + c], acc[i][j]);
        }
    }
}

// ---------------- K0: W2 = w_proj @ Wv ----------------
__global__ void __launch_bounds__(256)
k_w2(const float* __restrict__ w_proj, const float* __restrict__ w_qkv)
{
    const int m0 = blockIdx.y * 128;
    const int n0 = blockIdx.x * 128;
    const float* A  = w_proj + (size_t)m0 * CC;
    const float* Bm = w_qkv + (size_t)2 * CC * CC + n0;   // Wv

    float acc[8][8] = {};
    core128<false, false>(A, CC, Bm, CC, nullptr, 0, CC, acc);

    const int tx = threadIdx.x & 15, ty = threadIdx.x >> 4;
    #pragma unroll
    for (int i = 0; i < 8; i++) {
        const int r = m0 + rc_map(ty, i);
        *(float4*)&g_W2[r * CC + n0 + (tx << 2)]      = make_float4(acc[i][0], acc[i][1], acc[i][2], acc[i][3]);
        *(float4*)&g_W2[r * CC + n0 + 64 + (tx << 2)] = make_float4(acc[i][4], acc[i][5], acc[i][6], acc[i][7]);
    }
}

// ---------------- K3: R[b] = St[b] @ diag(1/rowsum) @ Wq ----------------
__global__ void __launch_bounds__(256)
k_r(const float* __restrict__ w_qkv)
{
    const int b  = blockIdx.z;
    const int e0 = blockIdx.y * 128;
    const int f0 = blockIdx.x * 128;
    const float* A  = g_St + (size_t)b * CC * CC + (size_t)e0 * CC;
    const float* Bm = w_qkv + f0;                         // Wq rows 0..255
    const float* sc = g_rowsum + b * CC;                  // reciprocals

    float acc[8][8] = {};
    core128<false, true>(A, CC, Bm, CC, sc, 0, CC, acc);

    const int tx = threadIdx.x & 15, ty = threadIdx.x >> 4;
    float* Rb = g_R + (size_t)b * CC * CC;
    #pragma unroll
    for (int i = 0; i < 8; i++) {
        const int r = e0 + rc_map(ty, i);
        *(float4*)&Rb[r * CC + f0 + (tx << 2)]      = make_float4(acc[i][0], acc[i][1], acc[i][2], acc[i][3]);
        *(float4*)&Rb[r * CC + f0 + 64 + (tx << 2)] = make_float4(acc[i][4], acc[i][5], acc[i][6], acc[i][7]);
    }
}

// ---------------- K4: M[b] = diag(inv) @ (W2 @ R[b]) ----------------
__global__ void __launch_bounds__(256)
k_m(const float* __restrict__ gamma, const float* __restrict__ var)
{
    const int b  = blockIdx.z;
    const int o0 = blockIdx.y * 128;
    const int f0 = blockIdx.x * 128;
    const float* A  = g_W2 + (size_t)o0 * CC;
    const float* Bm = g_R + (size_t)b * CC * CC + f0;

    float acc[8][8] = {};
    core128<false, false>(A, CC, Bm, CC, nullptr, 0, CC, acc);

    const int tx = threadIdx.x & 15, ty = threadIdx.x >> 4;
    float* Mb = g_M + (size_t)b * CC * CC;
    #pragma unroll
    for (int i = 0; i < 8; i++) {
        const int o = o0 + rc_map(ty, i);
        const float inv = gamma[o] * rsqrtf(var[o] + EPS);
        *(float4*)&Mb[o * CC + f0 + (tx << 2)] =
            make_float4(inv * acc[i][0], inv * acc[i][1], inv * acc[i][2], inv * acc[i][3]);
        *(float4*)&Mb[o * CC + f0 + 64 + (tx << 2)] =
            make_float4(inv * acc[i][4], inv * acc[i][5], inv * acc[i][6], inv * acc[i][7]);
    }
}

// ---------------- K5: out = relu(M @ x + bias) ----------------
__global__ void __launch_bounds__(256)
k_out(const float* __restrict__ x,
      const float* __restrict__ gamma, const float* __restrict__ beta,
      const float* __restrict__ mean,  const float* __restrict__ var,
      float* __restrict__ out)
{
    const int b  = blockIdx.z;
    const int o0 = blockIdx.y * 128;
    const int n0 = blockIdx.x * 128;
    const float* A  = g_M + (size_t)b * CC * CC + (size_t)o0 * CC;
    const float* Bm = x + (size_t)b * CC * NSP + n0;

    float acc[8][8] = {};
    core128<false, false>(A, CC, Bm, NSP, nullptr, 0, CC, acc);

    const int tx = threadIdx.x & 15, ty = threadIdx.x >> 4;
    float* Ob = out + (size_t)b * CC * NSP;
    #pragma unroll
    for (int i = 0; i < 8; i++) {
        const int o = o0 + rc_map(ty, i);
        const float inv  = gamma[o] * rsqrtf(var[o] + EPS);
        const float bias = beta[o] - mean[o] * inv;
        float4 v0, v1;
        v0.x = fmaxf(acc[i][0] + bias, 0.0f); v0.y = fmaxf(acc[i][1] + bias, 0.0f);
        v0.z = fmaxf(acc[i][2] + bias, 0.0f); v0.w = fmaxf(acc[i][3] + bias, 0.0f);
        v1.x = fmaxf(acc[i][4] + bias, 0.0f); v1.y = fmaxf(acc[i][5] + bias, 0.0f);
        v1.z = fmaxf(acc[i][6] + bias, 0.0f); v1.w = fmaxf(acc[i][7] + bias, 0.0f);
        *(float4*)(Ob + (size_t)o * NSP + n0 + (tx << 2))      = v0;
        *(float4*)(Ob + (size_t)o * NSP + n0 + 64 + (tx << 2)) = v1;
    }
}

// ---------------- launch ----------------
extern "C" void kernel_launch(void* const* d_in, const int* in_sizes, int n_in,
                              void* d_out, int out_size)
{
    const float* x      = (const float*)d_in[0];
    const float* w_qkv  = (const float*)d_in[1];
    const float* w_proj = (const float*)d_in[2];
    const float* gamma  = (const float*)d_in[3];
    const float* beta   = (const float*)d_in[4];
    const float* mean   = (const float*)d_in[5];
    const float* var    = (const float*)d_in[6];
    float* out = (float*)d_out;

    void* p_rowsum = nullptr;
    void* p_st     = nullptr;
    cudaGetSymbolAddress(&p_rowsum, g_rowsum);
    cudaGetSymbolAddress(&p_st, g_St);
    cudaMemsetAsync(p_rowsum, 0, (size_t)BB * CC * sizeof(float));
    cudaMemsetAsync(p_st, 0, (size_t)BB * CC * CC * sizeof(float));

    dim3 blk(256);

    // E = exp(Wk @ x) + rowsums
    k_exp<<<dim3(NSP / 128, CC / 128, BB), blk>>>(x, w_qkv);
    // invert rowsums
    k_inv<<<dim3(BB), dim3(256)>>>();
    // St = x @ E^T (split-K atomics)
    k_st<<<dim3(CC / 128, CC / 128, BB * KSPLIT), blk>>>(x);
    // W2 = w_proj @ Wv (batch independent)
    k_w2<<<dim3(CC / 128, CC / 128, 1), blk>>>(w_proj, w_qkv);
    // R = St @ diag(1/rowsum) @ Wq
    k_r<<<dim3(CC / 128, CC / 128, BB), blk>>>(w_qkv);
    // M = diag(inv) @ (W2 @ R)
    k_m<<<dim3(CC / 128, CC / 128, BB), blk>>>(gamma, var);
    // out = relu(M @ x + bias)
    k_out<<<dim3(NSP / 128, CC / 128, BB), blk>>>(x, gamma, beta, mean, var, out);
}

// round 2
// speedup vs baseline: 1.3934x; 1.3934x over previous
#include <cuda_runtime.h>
#include <cuda_bf16.h>
#include <math.h>
#include <stdint.h>

#define CC   256
#define NSP  16384
#define BB   8
#define EPS  1e-5f
#define KSPLIT 8

// ---------------- scratch (device globals; no allocs allowed) ----------------
__device__ __nv_bfloat16 g_Eh[(size_t)BB * CC * NSP];   // exp(Wk@x) hi  64MB
__device__ __nv_bfloat16 g_El[(size_t)BB * CC * NSP];   // exp(Wk@x) lo  64MB
__device__ float g_rowsum[BB * CC];
__device__ float g_St[BB * CC * CC];
__device__ float g_R[BB * CC * CC];
__device__ float g_W2[CC * CC];
__device__ __nv_bfloat16 g_Wkh[CC * CC], g_Wkl[CC * CC];
__device__ __nv_bfloat16 g_Mh[BB * CC * CC], g_Ml[BB * CC * CC];

// ---------------- mma/ldmatrix helpers ----------------
__device__ __forceinline__ void ldm4(uint32_t* r, const void* p) {
    uint32_t a = (uint32_t)__cvta_generic_to_shared(p);
    asm volatile("ldmatrix.sync.aligned.m8n8.x4.shared.b16 {%0,%1,%2,%3},[%4];"
                 : "=r"(r[0]), "=r"(r[1]), "=r"(r[2]), "=r"(r[3]) : "r"(a));
}
__device__ __forceinline__ void ldm2(uint32_t* r, const void* p) {
    uint32_t a = (uint32_t)__cvta_generic_to_shared(p);
    asm volatile("ldmatrix.sync.aligned.m8n8.x2.shared.b16 {%0,%1},[%2];"
                 : "=r"(r[0]), "=r"(r[1]) : "r"(a));
}
__device__ __forceinline__ void ldm2t(uint32_t* r, const void* p) {
    uint32_t a = (uint32_t)__cvta_generic_to_shared(p);
    asm volatile("ldmatrix.sync.aligned.m8n8.x2.trans.shared.b16 {%0,%1},[%2];"
                 : "=r"(r[0]), "=r"(r[1]) : "r"(a));
}
__device__ __forceinline__ void mma_bf(float* d, const uint32_t* a, const uint32_t* b) {
    asm volatile("mma.sync.aligned.m16n8k16.row.col.f32.bf16.bf16.f32 "
                 "{%0,%1,%2,%3},{%4,%5,%6,%7},{%8,%9},{%0,%1,%2,%3};"
                 : "+f"(d[0]), "+f"(d[1]), "+f"(d[2]), "+f"(d[3])
                 : "r"(a[0]), "r"(a[1]), "r"(a[2]), "r"(a[3]), "r"(b[0]), "r"(b[1]));
}
__device__ __forceinline__ __nv_bfloat16 bhi(float v) { return __float2bfloat16(v); }
__device__ __forceinline__ __nv_bfloat16 blo(float v, __nv_bfloat16 h) {
    return __float2bfloat16(v - __bfloat162float(h));
}

// ============================================================================
// NN core: D[128 m x 128 n] = sum_k A[m,k] * B[k,n]
//   A: bf16 hi/lo in gmem, row-major lda=CC (k contiguous)
//   B: fp32 in gmem (x), row-major ldb=NSP (n contiguous) -> split on the fly
//   3-pass: Ah*Bh + Ah*Bl + Al*Bh  (fp32 accumulate)
// ============================================================================
__device__ __forceinline__ void nn_core(
    __nv_bfloat16* Ah_s, __nv_bfloat16* Al_s,       // [128*40]
    __nv_bfloat16* Bh_s, __nv_bfloat16* Bl_s,       // [32*136]
    const __nv_bfloat16* __restrict__ Agh, const __nv_bfloat16* __restrict__ Agl,
    const float* __restrict__ Bg,
    float acc[4][4][4])
{
    const int t = threadIdx.x, lane = t & 31, w = t >> 5;
    const int wm = w & 1, wn = w >> 1;
    const int ar = wm * 64 + (lane & 15);
    const int ac = (lane >> 4) * 8;
    const int btr = lane & 15;
    const int btc = wn * 32;

    for (int k0 = 0; k0 < CC; k0 += 32) {
        __syncthreads();
        {   // A: 128 rows x 32 bf16 (hi & lo arrays)
            const int r = t >> 1, p = t & 1;
            union { uint4 u; __nv_bfloat16 h[8]; } v0, v1, v2, v3;
            v0.u = *(const uint4*)(Agh + (size_t)r * CC + k0 + p * 16);
            v1.u = *(const uint4*)(Agh + (size_t)r * CC + k0 + p * 16 + 8);
            v2.u = *(const uint4*)(Agl + (size_t)r * CC + k0 + p * 16);
            v3.u = *(const uint4*)(Agl + (size_t)r * CC + k0 + p * 16 + 8);
            #pragma unroll
            for (int i = 0; i < 8; i++) {
                Ah_s[r * 40 + p * 16 + i]     = v0.h[i];
                Ah_s[r * 40 + p * 16 + 8 + i] = v1.h[i];
                Al_s[r * 40 + p * 16 + i]     = v2.h[i];
                Al_s[r * 40 + p * 16 + 8 + i] = v3.h[i];
            }
            // B: 32 rows (k) x 128 (n) fp32 -> bf16 hi/lo
            const int kr = t >> 3, c0 = (t & 7) * 16;
            const float* bp = Bg + (size_t)(k0 + kr) * NSP + c0;
            #pragma unroll
            for (int j = 0; j < 4; j++) {
                float4 f = *(const float4*)(bp + 4 * j);
                float vv[4] = {f.x, f.y, f.z, f.w};
                #pragma unroll
                for (int i = 0; i < 4; i++) {
                    __nv_bfloat16 h = bhi(vv[i]);
                    Bh_s[kr * 136 + c0 + 4 * j + i] = h;
                    Bl_s[kr * 136 + c0 + 4 * j + i] = blo(vv[i], h);
                }
            }
        }
        __syncthreads();

        #pragma unroll
        for (int pass = 0; pass < 3; pass++) {
            const __nv_bfloat16* As = (pass == 2) ? Al_s : Ah_s;
            const __nv_bfloat16* Bs = (pass == 1) ? Bl_s : Bh_s;
            #pragma unroll
            for (int kk = 0; kk < 2; kk++) {
                uint32_t af[4][4], bf[4][2];
                #pragma unroll
                for (int mi = 0; mi < 4; mi++)
                    ldm4(af[mi], As + (ar + mi * 16) * 40 + kk * 16 + ac);
                #pragma unroll
                for (int ni = 0; ni < 4; ni++)
                    ldm2t(bf[ni], Bs + (kk * 16 + btr) * 136 + btc + ni * 8);
                #pragma unroll
                for (int mi = 0; mi < 4; mi++)
                    #pragma unroll
                    for (int ni = 0; ni < 4; ni++)
                        mma_bf(acc[mi][ni], af[mi], bf[ni]);
            }
        }
    }
}

// ============================================================================
// NT core (k_st): D[128 e x 128 c] = sum_n A[e,n]*B[c,n], both n-contiguous
//   A: fp32 x rows (split on the fly), B: bf16 hi/lo E rows
//   3-pass: Ah*Bh + Al*Bh + Ah*Bl
// ============================================================================
__device__ __forceinline__ void nt_core(
    __nv_bfloat16* Ah_s, __nv_bfloat16* Al_s,       // [128*40]
    __nv_bfloat16* Bh_s, __nv_bfloat16* Bl_s,       // [128*40]
    const float* __restrict__ Ag,
    const __nv_bfloat16* __restrict__ Bgh, const __nv_bfloat16* __restrict__ Bgl,
    int kbeg, int kend, float acc[4][4][4])
{
    const int t = threadIdx.x, lane = t & 31, w = t >> 5;
    const int wm = w & 1, wn = w >> 1;
    const int ar = wm * 64 + (lane & 15);
    const int ac = (lane >> 4) * 8;
    const int nr = wn * 32 + (lane & 7);
    const int nc = ((lane >> 3) & 1) * 8;

    for (int k0 = kbeg; k0 < kend; k0 += 32) {
        __syncthreads();
        {
            const int r = t >> 1, p = t & 1;
            // A: x fp32, 16 floats per thread -> hi/lo
            const float* ap = Ag + (size_t)r * NSP + k0 + p * 16;
            #pragma unroll
            for (int j = 0; j < 4; j++) {
                float4 f = *(const float4*)(ap + 4 * j);
                float vv[4] = {f.x, f.y, f.z, f.w};
                #pragma unroll
                for (int i = 0; i < 4; i++) {
                    __nv_bfloat16 h = bhi(vv[i]);
                    Ah_s[r * 40 + p * 16 + 4 * j + i] = h;
                    Al_s[r * 40 + p * 16 + 4 * j + i] = blo(vv[i], h);
                }
            }
            // B: E bf16 hi/lo, 16 elems per thread each
            union { uint4 u; __nv_bfloat16 h[8]; } u0, u1, u2, u3;
            const __nv_bfloat16* bph = Bgh + (size_t)r * NSP + k0 + p * 16;
            const __nv_bfloat16* bpl = Bgl + (size_t)r * NSP + k0 + p * 16;
            u0.u = *(const uint4*)(bph);     u1.u = *(const uint4*)(bph + 8);
            u2.u = *(const uint4*)(bpl);     u3.u = *(const uint4*)(bpl + 8);
            #pragma unroll
            for (int i = 0; i < 8; i++) {
                Bh_s[r * 40 + p * 16 + i]     = u0.h[i];
                Bh_s[r * 40 + p * 16 + 8 + i] = u1.h[i];
                Bl_s[r * 40 + p * 16 + i]     = u2.h[i];
                Bl_s[r * 40 + p * 16 + 8 + i] = u3.h[i];
            }
        }
        __syncthreads();

        #pragma unroll
        for (int pass = 0; pass < 3; pass++) {
            const __nv_bfloat16* As = (pass == 1) ? Al_s : Ah_s;
            const __nv_bfloat16* Bs = (pass == 2) ? Bl_s : Bh_s;
            #pragma unroll
            for (int kk = 0; kk < 2; kk++) {
                uint32_t af[4][4], bf[4][2];
                #pragma unroll
                for (int mi = 0; mi < 4; mi++)
                    ldm4(af[mi], As + (ar + mi * 16) * 40 + kk * 16 + ac);
                #pragma unroll
                for (int ni = 0; ni < 4; ni++)
                    ldm2(bf[ni], Bs + (nr + ni * 8) * 40 + kk * 16 + nc);
                #pragma unroll
                for (int mi = 0; mi < 4; mi++)
                    #pragma unroll
                    for (int ni = 0; ni < 4; ni++)
                        mma_bf(acc[mi][ni], af[mi], bf[ni]);
            }
        }
    }
}

// ---------------- K prep: split Wk to bf16 hi/lo ----------------
__global__ void k_prep(const float* __restrict__ w_qkv)
{
    int i = blockIdx.x * 256 + threadIdx.x;
    if (i < CC * CC) {
        float v = w_qkv[CC * CC + i];           // Wk rows
        __nv_bfloat16 h = bhi(v);
        g_Wkh[i] = h;
        g_Wkl[i] = blo(v, h);
    }
}

// ---------------- K1: E = exp(Wk @ x) + rowsums ----------------
__global__ void __launch_bounds__(256)
k_exp(const float* __restrict__ x)
{
    __shared__ __align__(16) __nv_bfloat16 Ah_s[128 * 40], Al_s[128 * 40];
    __shared__ __align__(16) __nv_bfloat16 Bh_s[32 * 136], Bl_s[32 * 136];

    const int b = blockIdx.z, m0 = blockIdx.y * 128, n0 = blockIdx.x * 128;
    float acc[4][4][4];
    #pragma unroll
    for (int a = 0; a < 4; a++)
        #pragma unroll
        for (int c = 0; c < 4; c++)
            #pragma unroll
            for (int d = 0; d < 4; d++) acc[a][c][d] = 0.f;

    nn_core(Ah_s, Al_s, Bh_s, Bl_s,
            g_Wkh + (size_t)m0 * CC, g_Wkl + (size_t)m0 * CC,
            x + (size_t)b * CC * NSP + n0, acc);

    const int t = threadIdx.x, lane = t & 31, w = t >> 5;
    const int wm = w & 1, wn = w >> 1;
    const int rbase = m0 + wm * 64 + (lane >> 2);
    const int cbase = n0 + wn * 32 + (lane & 3) * 2;
    __nv_bfloat16* Eh = g_Eh + (size_t)b * CC * NSP;
    __nv_bfloat16* El = g_El + (size_t)b * CC * NSP;

    float rs[8] = {0, 0, 0, 0, 0, 0, 0, 0};
    #pragma unroll
    for (int mi = 0; mi < 4; mi++)
        #pragma unroll
        for (int h = 0; h < 2; h++) {
            const int rr = rbase + mi * 16 + 8 * h;
            #pragma unroll
            for (int ni = 0; ni < 4; ni++)
                #pragma unroll
                for (int c2 = 0; c2 < 2; c2++) {
                    float e = __expf(acc[mi][ni][2 * h + c2]);
                    const int cc = cbase + ni * 8 + c2;
                    size_t off = (size_t)rr * NSP + cc;
                    __nv_bfloat16 eh = bhi(e);
                    Eh[off] = eh;
                    El[off] = blo(e, eh);
                    rs[mi * 2 + h] += e;
                }
        }
    #pragma unroll
    for (int i = 0; i < 8; i++) {
        float v = rs[i];
        v += __shfl_xor_sync(0xffffffffu, v, 1);
        v += __shfl_xor_sync(0xffffffffu, v, 2);
        if ((lane & 3) == 0) {
            const int rr = rbase + (i >> 1) * 16 + 8 * (i & 1);
            atomicAdd(&g_rowsum[b * CC + rr], v);
        }
    }
}

// ---------------- invert rowsums ----------------
__global__ void k_inv()
{
    int i = blockIdx.x * 256 + threadIdx.x;
    if (i < BB * CC) g_rowsum[i] = 1.0f / g_rowsum[i];
}

// ---------------- K2: St[e][c] += sum_n x[e,n]*E[c,n] (split-K) ----------------
__global__ void __launch_bounds__(256)
k_st(const float* __restrict__ x)
{
    __shared__ __align__(16) __nv_bfloat16 Ah_s[128 * 40], Al_s[128 * 40];
    __shared__ __align__(16) __nv_bfloat16 Bh_s[128 * 40], Bl_s[128 * 40];

    const int c0 = blockIdx.x * 128, e0 = blockIdx.y * 128;
    const int b = blockIdx.z >> 3, ks = blockIdx.z & 7;
    const int kbeg = ks * (NSP / KSPLIT);

    float acc[4][4][4];
    #pragma unroll
    for (int a = 0; a < 4; a++)
        #pragma unroll
        for (int c = 0; c < 4; c++)
            #pragma unroll
            for (int d = 0; d < 4; d++) acc[a][c][d] = 0.f;

    nt_core(Ah_s, Al_s, Bh_s, Bl_s,
            x + (size_t)(b * CC + e0) * NSP,
            g_Eh + (size_t)(b * CC + c0) * NSP,
            g_El + (size_t)(b * CC + c0) * NSP,
            kbeg, kbeg + NSP / KSPLIT, acc);

    const int t = threadIdx.x, lane = t & 31, w = t >> 5;
    const int wm = w & 1, wn = w >> 1;
    const int rbase = e0 + wm * 64 + (lane >> 2);
    const int cbase = c0 + wn * 32 + (lane & 3) * 2;
    float* Sb = g_St + (size_t)b * CC * CC;

    #pragma unroll
    for (int mi = 0; mi < 4; mi++)
        #pragma unroll
        for (int h = 0; h < 2; h++) {
            const int rr = rbase + mi * 16 + 8 * h;
            #pragma unroll
            for (int ni = 0; ni < 4; ni++)
                #pragma unroll
                for (int c2 = 0; c2 < 2; c2++)
                    atomicAdd(&Sb[rr * CC + cbase + ni * 8 + c2], acc[mi][ni][2 * h + c2]);
        }
}

// ---------------- fp32 64x64 core for the small middle GEMMs ----------------
template<bool BSCALE>
__device__ __forceinline__ void core64(
    const float* __restrict__ A, int lda,
    const float* __restrict__ B, int ldb,
    const float* __restrict__ bscale, float acc[4][4])
{
    __shared__ __align__(16) float As[16][68];
    __shared__ __align__(16) float Bs[16][68];
    const int t = threadIdx.x, tx = t & 15, ty = t >> 4;

    for (int k0 = 0; k0 < CC; k0 += 16) {
        __syncthreads();
        {
            const int r = t >> 2, q = t & 3;
            float4 a4 = *(const float4*)(A + (size_t)r * lda + k0 + 4 * q);
            As[4 * q + 0][r] = a4.x; As[4 * q + 1][r] = a4.y;
            As[4 * q + 2][r] = a4.z; As[4 * q + 3][r] = a4.w;
            const int kr = t >> 4, c0 = (t & 15) * 4;
            float4 b4 = *(const float4*)(B + (size_t)(k0 + kr) * ldb + c0);
            if (BSCALE) {
                float s = bscale[k0 + kr];
                b4.x *= s; b4.y *= s; b4.z *= s; b4.w *= s;
            }
            *(float4*)&Bs[kr][c0] = b4;
        }
        __syncthreads();
        #pragma unroll
        for (int k = 0; k < 16; k++) {
            float4 a4 = *(const float4*)&As[k][ty * 4];
            float4 b4 = *(const float4*)&Bs[k][tx * 4];
            float av[4] = {a4.x, a4.y, a4.z, a4.w};
            float bv[4] = {b4.x, b4.y, b4.z, b4.w};
            #pragma unroll
            for (int i = 0; i < 4; i++)
                #pragma unroll
                for (int j = 0; j < 4; j++)
                    acc[i][j] += av[i] * bv[j];
        }
    }
}

// ---------------- K0: W2 = w_proj @ Wv ----------------
__global__ void __launch_bounds__(256)
k_w2(const float* __restrict__ w_proj, const float* __restrict__ w_qkv)
{
    const int m0 = blockIdx.y * 64, n0 = blockIdx.x * 64;
    float acc[4][4] = {};
    core64<false>(w_proj + (size_t)m0 * CC, CC,
                  w_qkv + (size_t)2 * CC * CC + n0, CC, nullptr, acc);
    const int tx = threadIdx.x & 15, ty = threadIdx.x >> 4;
    #pragma unroll
    for (int i = 0; i < 4; i++)
        #pragma unroll
        for (int j = 0; j < 4; j++)
            g_W2[(m0 + ty * 4 + i) * CC + n0 + tx * 4 + j] = acc[i][j];
}

// ---------------- K3: R = St @ diag(1/rowsum) @ Wq ----------------
__global__ void __launch_bounds__(256)
k_r(const float* __restrict__ w_qkv)
{
    const int b = blockIdx.z, m0 = blockIdx.y * 64, n0 = blockIdx.x * 64;
    float acc[4][4] = {};
    core64<true>(g_St + (size_t)b * CC * CC + (size_t)m0 * CC, CC,
                 w_qkv + n0, CC, g_rowsum + b * CC, acc);
    const int tx = threadIdx.x & 15, ty = threadIdx.x >> 4;
    float* Rb = g_R + (size_t)b * CC * CC;
    #pragma unroll
    for (int i = 0; i < 4; i++)
        #pragma unroll
        for (int j = 0; j < 4; j++)
            Rb[(m0 + ty * 4 + i) * CC + n0 + tx * 4 + j] = acc[i][j];
}

// ---------------- K4: M = diag(inv) @ (W2 @ R), emit bf16 hi/lo ----------------
__global__ void __launch_bounds__(256)
k_m(const float* __restrict__ gamma, const float* __restrict__ var)
{
    const int b = blockIdx.z, m0 = blockIdx.y * 64, n0 = blockIdx.x * 64;
    float acc[4][4] = {};
    core64<false>(g_W2 + (size_t)m0 * CC, CC,
                  g_R + (size_t)b * CC * CC + n0, CC, nullptr, acc);
    const int tx = threadIdx.x & 15, ty = threadIdx.x >> 4;
    __nv_bfloat16* Mh = g_Mh + (size_t)b * CC * CC;
    __nv_bfloat16* Ml = g_Ml + (size_t)b * CC * CC;
    #pragma unroll
    for (int i = 0; i < 4; i++) {
        const int o = m0 + ty * 4 + i;
        const float inv = gamma[o] * rsqrtf(var[o] + EPS);
        #pragma unroll
        for (int j = 0; j < 4; j++) {
            float v = inv * acc[i][j];
            __nv_bfloat16 h = bhi(v);
            Mh[o * CC + n0 + tx * 4 + j] = h;
            Ml[o * CC + n0 + tx * 4 + j] = blo(v, h);
        }
    }
}

// ---------------- K5: out = relu(M @ x + bias) ----------------
__global__ void __launch_bounds__(256)
k_out(const float* __restrict__ x,
      const float* __restrict__ gamma, const float* __restrict__ beta,
      const float* __restrict__ mean,  const float* __restrict__ var,
      float* __restrict__ out)
{
    __shared__ __align__(16) __nv_bfloat16 Ah_s[128 * 40], Al_s[128 * 40];
    __shared__ __align__(16) __nv_bfloat16 Bh_s[32 * 136], Bl_s[32 * 136];

    const int b = blockIdx.z, m0 = blockIdx.y * 128, n0 = blockIdx.x * 128;
    float acc[4][4][4];
    #pragma unroll
    for (int a = 0; a < 4; a++)
        #pragma unroll
        for (int c = 0; c < 4; c++)
            #pragma unroll
            for (int d = 0; d < 4; d++) acc[a][c][d] = 0.f;

    nn_core(Ah_s, Al_s, Bh_s, Bl_s,
            g_Mh + (size_t)b * CC * CC + (size_t)m0 * CC,
            g_Ml + (size_t)b * CC * CC + (size_t)m0 * CC,
            x + (size_t)b * CC * NSP + n0, acc);

    const int t = threadIdx.x, lane = t & 31, w = t >> 5;
    const int wm = w & 1, wn = w >> 1;
    const int rbase = m0 + wm * 64 + (lane >> 2);
    const int cbase = n0 + wn * 32 + (lane & 3) * 2;
    float* Ob = out + (size_t)b * CC * NSP;

    #pragma unroll
    for (int mi = 0; mi < 4; mi++)
        #pragma unroll
        for (int h = 0; h < 2; h++) {
            const int o = rbase + mi * 16 + 8 * h;
            const float inv  = gamma[o] * rsqrtf(var[o] + EPS);
            const float bias = beta[o] - mean[o] * inv;
            #pragma unroll
            for (int ni = 0; ni < 4; ni++)
                #pragma unroll
                for (int c2 = 0; c2 < 2; c2++) {
                    float v = fmaxf(acc[mi][ni][2 * h + c2] + bias, 0.0f);
                    Ob[(size_t)o * NSP + cbase + ni * 8 + c2] = v;
                }
        }
}

// ---------------- launch ----------------
extern "C" void kernel_launch(void* const* d_in, const int* in_sizes, int n_in,
                              void* d_out, int out_size)
{
    const float* x      = (const float*)d_in[0];
    const float* w_qkv  = (const float*)d_in[1];
    const float* w_proj = (const float*)d_in[2];
    const float* gamma  = (const float*)d_in[3];
    const float* beta   = (const float*)d_in[4];
    const float* mean   = (const float*)d_in[5];
    const float* var    = (const float*)d_in[6];
    float* out = (float*)d_out;

    void* p_rowsum = nullptr;
    void* p_st     = nullptr;
    cudaGetSymbolAddress(&p_rowsum, g_rowsum);
    cudaGetSymbolAddress(&p_st, g_St);
    cudaMemsetAsync(p_rowsum, 0, (size_t)BB * CC * sizeof(float));
    cudaMemsetAsync(p_st, 0, (size_t)BB * CC * CC * sizeof(float));

    dim3 blk(256);

    k_prep<<<dim3(CC * CC / 256), blk>>>(w_qkv);
    k_w2<<<dim3(4, 4), blk>>>(w_proj, w_qkv);                 // independent
    k_exp<<<dim3(NSP / 128, CC / 128, BB), blk>>>(x);
    k_inv<<<dim3(BB), blk>>>();
    k_st<<<dim3(CC / 128, CC / 128, BB * KSPLIT), blk>>>(x);
    k_r<<<dim3(4, 4, BB), blk>>>(w_qkv);
    k_m<<<dim3(4, 4, BB), blk>>>(gamma, var);
    k_out<<<dim3(NSP / 128, CC / 128, BB), blk>>>(x, gamma, beta, mean, var, out);
}